// round 9
// baseline (speedup 1.0000x reference)
#include <cuda_runtime.h>
#include <cstdint>
#include <cmath>

#define B_ 128
#define T_ 512
#define I_ 256
#define H_ 512
#define NCTA 128
#define GRP 64          // CTAs per barrier group (one per b-slice)

// ---- static device scratch ----
__device__ float  g_xproj[(size_t)4 * T_ * B_ * H_];   // [g][t][b][h]
__device__ float2 g_hT[2][H_][B_];                     // h duplicated {v,v}, h-major
__device__ unsigned g_cnt[2][32];                      // per-group barrier counter (padded)
__device__ unsigned g_sns[2][32];                      // per-group barrier sense

// ---- packed fp32x2 FMA ----
__device__ __forceinline__ void fma2(unsigned long long& d,
                                     unsigned long long a,
                                     unsigned long long b) {
    asm("fma.rn.f32x2 %0, %1, %2, %0;" : "+l"(d) : "l"(a), "l"(b));
}
__device__ __forceinline__ float lo32(unsigned long long v) {
    return __uint_as_float((unsigned)(v & 0xffffffffull));
}
__device__ __forceinline__ float hi32(unsigned long long v) {
    return __uint_as_float((unsigned)(v >> 32));
}
__device__ __forceinline__ float rcpa(float x) {
    float r;
    asm("rcp.approx.f32 %0, %1;" : "=f"(r) : "f"(x));
    return r;
}
// rational tanh numerator/denominator (Eigen coefficients, float-accurate)
__device__ __forceinline__ void tanh_pq(float x, float& p, float& q) {
    x = fminf(fmaxf(x, -7.90531110763549805f), 7.90531110763549805f);
    float x2 = x * x;
    float pp = fmaf(x2, -2.76076847742355e-16f, 2.00018790482477e-13f);
    pp = fmaf(pp, x2, -8.60467152213735e-11f);
    pp = fmaf(pp, x2, 5.12229709037114e-08f);
    pp = fmaf(pp, x2, 1.48572235717979e-05f);
    pp = fmaf(pp, x2, 6.37261928875436e-04f);
    pp = fmaf(pp, x2, 4.89352455891786e-03f);
    p = pp * x;
    float qq = fmaf(x2, 1.19825839466702e-06f, 1.18534705686654e-04f);
    qq = fmaf(qq, x2, 2.26843463243900e-03f);
    q = fmaf(qq, x2, 4.89352518554385e-03f);
}
// 4 divisions sharing one rcp.approx
__device__ __forceinline__ void div4(const float* p, const float* q, float* o) {
    float q01 = q[0] * q[1], q23 = q[2] * q[3];
    float r   = rcpa(q01 * q23);
    float r01 = q23 * r, r23 = q01 * r;
    o[0] = p[0] * (q[1] * r01);
    o[1] = p[1] * (q[0] * r01);
    o[2] = p[2] * (q[3] * r23);
    o[3] = p[3] * (q[2] * r23);
}
__device__ __forceinline__ void cpa16(void* sdst, const void* gsrc) {
    unsigned s = (unsigned)__cvta_generic_to_shared(sdst);
    asm volatile("cp.async.cg.shared.global [%0], [%1], 16;" :: "r"(s), "l"(gsrc));
}

// ---------------------------------------------------------------------------
__global__ void lstm_reset() {
    int i = threadIdx.x;
    if (i < 2) { g_cnt[i][0] = 0; g_sns[i][0] = 0; }
}

// ---------------------------------------------------------------------------
// projection GEMM (proven in R6/R7): g_xproj[g][t][b][h] = x.W_g^T + b_g
// ---------------------------------------------------------------------------
__global__ __launch_bounds__(128) void lstm_proj(
    const float* __restrict__ x,
    const float* __restrict__ Wz, const float* __restrict__ Ws,
    const float* __restrict__ Wf, const float* __restrict__ Wo,
    const float* __restrict__ bz, const float* __restrict__ bs,
    const float* __restrict__ bf, const float* __restrict__ bo)
{
    __shared__ __align__(16) float2 As2[32][64];
    __shared__ __align__(16) float  Bs[32][64];

    const int tid = threadIdx.x;
    const int r0  = blockIdx.x * 64;
    const int n0  = blockIdx.y * 64;
    const int g   = n0 >> 9;
    const int h0  = n0 & 511;

    const float* W    = (g == 0) ? Wz : (g == 1) ? Ws : (g == 2) ? Wf : Wo;
    const float* bias = (g == 0) ? bz : (g == 1) ? bs : (g == 2) ? bf : bo;

    const int tn = tid & 7;
    const int tm = tid >> 3;
    const int lm = tid & 63;
    const int qb = (tid >> 6) * 4;
    const float* xr = x + (size_t)(r0 + lm) * I_;
    const float* wr = W + (size_t)(h0 + lm) * I_;

    unsigned long long acc[4][4];
#pragma unroll
    for (int i = 0; i < 4; i++)
#pragma unroll
        for (int j = 0; j < 4; j++) acc[i][j] = 0ull;

    float4 pa[4], pw[4];
#pragma unroll
    for (int i = 0; i < 4; i++) {
        pa[i] = *(const float4*)(xr + (qb + i) * 4);
        pw[i] = *(const float4*)(wr + (qb + i) * 4);
    }

    for (int kt = 0; kt < I_ / 32; kt++) {
#pragma unroll
        for (int i = 0; i < 4; i++) {
            int q = qb + i;
            As2[q * 4 + 0][lm] = make_float2(pa[i].x, pa[i].x);
            As2[q * 4 + 1][lm] = make_float2(pa[i].y, pa[i].y);
            As2[q * 4 + 2][lm] = make_float2(pa[i].z, pa[i].z);
            As2[q * 4 + 3][lm] = make_float2(pa[i].w, pa[i].w);
            Bs[q * 4 + 0][lm] = pw[i].x;
            Bs[q * 4 + 1][lm] = pw[i].y;
            Bs[q * 4 + 2][lm] = pw[i].z;
            Bs[q * 4 + 3][lm] = pw[i].w;
        }
        __syncthreads();
        if (kt + 1 < I_ / 32) {
            int k0 = (kt + 1) * 32;
#pragma unroll
            for (int i = 0; i < 4; i++) {
                pa[i] = *(const float4*)(xr + k0 + (qb + i) * 4);
                pw[i] = *(const float4*)(wr + k0 + (qb + i) * 4);
            }
        }
#pragma unroll
        for (int kk = 0; kk < 32; kk++) {
            ulonglong2 a01 = *(const ulonglong2*)&As2[kk][tm * 4];
            ulonglong2 a23 = *(const ulonglong2*)&As2[kk][tm * 4 + 2];
            ulonglong2 b01 = *(const ulonglong2*)&Bs[kk][tn * 8];
            ulonglong2 b23 = *(const ulonglong2*)&Bs[kk][tn * 8 + 4];
            fma2(acc[0][0], a01.x, b01.x); fma2(acc[0][1], a01.x, b01.y);
            fma2(acc[0][2], a01.x, b23.x); fma2(acc[0][3], a01.x, b23.y);
            fma2(acc[1][0], a01.y, b01.x); fma2(acc[1][1], a01.y, b01.y);
            fma2(acc[1][2], a01.y, b23.x); fma2(acc[1][3], a01.y, b23.y);
            fma2(acc[2][0], a23.x, b01.x); fma2(acc[2][1], a23.x, b01.y);
            fma2(acc[2][2], a23.x, b23.x); fma2(acc[2][3], a23.x, b23.y);
            fma2(acc[3][0], a23.y, b01.x); fma2(acc[3][1], a23.y, b01.y);
            fma2(acc[3][2], a23.y, b23.x); fma2(acc[3][3], a23.y, b23.y);
        }
        __syncthreads();
    }

    float bv[8];
#pragma unroll
    for (int j = 0; j < 8; j++) bv[j] = bias[h0 + tn * 8 + j];
#pragma unroll
    for (int i = 0; i < 4; i++) {
        int r  = r0 + tm * 4 + i;
        int bb = r >> 9;
        int tt = r & 511;
        float* orow = g_xproj + (((size_t)g * T_ + tt) * B_ + bb) * H_ + h0 + tn * 8;
#pragma unroll
        for (int jp = 0; jp < 4; jp++) {
            float2 v = make_float2(lo32(acc[i][jp]) + bv[jp * 2],
                                   hi32(acc[i][jp]) + bv[jp * 2 + 1]);
            *(float2*)(orow + jp * 2) = v;
        }
    }
}

// ---------------------------------------------------------------------------
// persistent recurrence. 128 CTAs x 256 thr. CTA: M=32 (4g x 8h), N=64 b, K=512.
//   Rsm   [512][32] fp32, resident (64KB)
//   Hs2   [2][64][64] float2 dup'd chunks via cp.async.cg (64KB)
//   actsm [32][66] activations (8.4KB)
// ---------------------------------------------------------------------------
__global__ __launch_bounds__(256, 1) void lstm_recur(
    const float* __restrict__ Rz, const float* __restrict__ Rs_,
    const float* __restrict__ Rf, const float* __restrict__ Ro,
    float* __restrict__ out)
{
    extern __shared__ float sm[];
    float*  Rsm   = sm;                            // [512][32]
    float2* Hs2   = (float2*)(sm + 512 * 32);      // [2][64][64]
    float*  actsm = sm + 512 * 32 + 2 * 64 * 64 * 2;  // [32][66]

    const int tid = threadIdx.x;
    const int cta = blockIdx.x;
    const int bg  = cta & 1;
    const int b0  = bg * 64;
    const int h0  = (cta >> 1) * 8;

    const int mg = tid & 7;        // m = mg*4, M=32
    const int ng = tid >> 3;       // n = ng*2, N=64
    const int gt = mg >> 1;        // this thread's gate (0..3)

    // ---- load R tile once: Rsm[k][m], m = g*8 + hr ----
    {
        int m  = tid & 31;
        int kq = (tid >> 5) * 64;
        int rg = m >> 3, hh = m & 7;
        const float* Rp = ((rg == 0) ? Rz : (rg == 1) ? Rs_ : (rg == 2) ? Rf : Ro)
                        + (size_t)(h0 + hh) * H_ + kq;
#pragma unroll 4
        for (int j = 0; j < 64; j += 4) {
            float4 v = *(const float4*)(Rp + j);
            Rsm[(kq + j + 0) * 32 + m] = v.x;
            Rsm[(kq + j + 1) * 32 + m] = v.y;
            Rsm[(kq + j + 2) * 32 + m] = v.z;
            Rsm[(kq + j + 3) * 32 + m] = v.w;
        }
    }
    __syncthreads();

    // combine identity: thread owns cells (b0+2*cb, h0+ch), (b0+2*cb+1, h0+ch)
    const int ch = tid >> 5;
    const int cb = tid & 31;
    float creg0 = 0.0f, creg1 = 0.0f;
    float hsum0 = 0.0f, hsum1 = 0.0f;

    // cp.async staging role: one 128B segment per thread per chunk
    const int srow = tid >> 2;
    const int sseg = (tid & 3) * 16;   // float2 offset within row

    for (int t = 0; t < T_; t++) {
        // prefetch xproj for this thread's 8 cells: [g][t][b0+ng*2+n][h0+(mg&1)*4 ..+3]
        float4 xq0, xq1;
        {
            const float* xb = g_xproj + (((size_t)gt * T_ + t) * B_ + b0 + ng * 2) * H_
                            + h0 + (mg & 1) * 4;
            xq0 = *(const float4*)xb;
            xq1 = *(const float4*)(xb + H_);
        }

        unsigned long long acc00 = 0, acc01 = 0, acc10 = 0, acc11 = 0;

        if (t > 0) {
            const float2* hsrc = &g_hT[t & 1][0][0];
            // prologue: chunk 0
            {
                const float2* s = hsrc + (size_t)srow * B_ + b0 + sseg;
                float2* d = Hs2 + (size_t)srow * 64 + sseg;
#pragma unroll
                for (int i = 0; i < 8; i++) cpa16(d + i * 2, s + i * 2);
                asm volatile("cp.async.commit_group;");
            }
            for (int c = 0; c < 8; c++) {
                asm volatile("cp.async.wait_group 0;");
                __syncthreads();
                if (c < 7) {
                    const float2* s = hsrc + (size_t)((c + 1) * 64 + srow) * B_ + b0 + sseg;
                    float2* d = Hs2 + (size_t)(((c + 1) & 1) * 64 + srow) * 64 + sseg;
#pragma unroll
                    for (int i = 0; i < 8; i++) cpa16(d + i * 2, s + i * 2);
                    asm volatile("cp.async.commit_group;");
                }
                const float* Rb = Rsm + (c * 64) * 32 + mg * 4;
                const float2* Hb = Hs2 + (size_t)((c & 1) * 64) * 64 + ng * 2;
#pragma unroll 8
                for (int kk = 0; kk < 64; kk++) {
                    ulonglong2 rp = *(const ulonglong2*)(Rb + kk * 32);
                    ulonglong2 hv = *(const ulonglong2*)(Hb + kk * 64);
                    fma2(acc00, rp.x, hv.x); fma2(acc01, rp.x, hv.y);
                    fma2(acc10, rp.y, hv.x); fma2(acc11, rp.y, hv.y);
                }
            }
        }

        // ---- epilogue: 8 pre-activations -> rational tanh/sigmoid ----
        {
            // order: idx = p*2 + half (m dimension), n in {0,1}
            float pre[8];
            pre[0] = lo32(acc00) + xq0.x;  pre[1] = hi32(acc00) + xq0.y;
            pre[2] = lo32(acc10) + xq0.z;  pre[3] = hi32(acc10) + xq0.w;
            pre[4] = lo32(acc01) + xq1.x;  pre[5] = hi32(acc01) + xq1.y;
            pre[6] = lo32(acc11) + xq1.z;  pre[7] = hi32(acc11) + xq1.w;

            const bool isz = (gt == 0);
            const float s1 = isz ? 1.0f : 0.5f;   // tanh(x) vs tanh(x/2)
            const float s3 = isz ? 0.0f : 0.5f;   // post fma: t*s1' + s3

            float pn[8], qn[8], av[8];
#pragma unroll
            for (int i = 0; i < 8; i++) tanh_pq(pre[i] * s1, pn[i], qn[i]);
            div4(pn,     qn,     av);
            div4(pn + 4, qn + 4, av + 4);
#pragma unroll
            for (int i = 0; i < 8; i++) av[i] = fmaf(av[i], s1 * 2.0f * s3 + (isz ? 1.0f : 0.0f), s3);
            // (isz: av*1+0 ; !isz: av*0.5+0.5)

            // store actsm[row = hr*4 + g][col = n]
#pragma unroll
            for (int i = 0; i < 8; i++) {
                int m  = mg * 4 + (i & 3);      // i&3 = p*2+half
                int n  = ng * 2 + (i >> 2);
                int hr = m & 7;
                actsm[(hr * 4 + gt) * 66 + n] = av[i];
            }
        }
        __syncthreads();

        // ---- combine: c,h update; write dup'd h; accumulate sum ----
        {
            float2 zv = *(const float2*)&actsm[(ch * 4 + 0) * 66 + cb * 2];
            float2 sv = *(const float2*)&actsm[(ch * 4 + 1) * 66 + cb * 2];
            float2 fv = *(const float2*)&actsm[(ch * 4 + 2) * 66 + cb * 2];
            float2 ov = *(const float2*)&actsm[(ch * 4 + 3) * 66 + cb * 2];
            float c0 = fmaf(sv.x, zv.x, fv.x * creg0);
            float c1 = fmaf(sv.y, zv.y, fv.y * creg1);
            creg0 = c0; creg1 = c1;
            // tanh(c0), tanh(c1) with shared rcp
            float p0, q0, p1, q1;
            tanh_pq(c0, p0, q0);
            tanh_pq(c1, p1, q1);
            float r  = rcpa(q0 * q1);
            float t0 = p0 * (q1 * r);
            float t1 = p1 * (q0 * r);
            float hn0 = ov.x * t0;
            float hn1 = ov.y * t1;
            hsum0 += hn0; hsum1 += hn1;
            float4 wv = make_float4(hn0, hn0, hn1, hn1);
            *(float4*)&g_hT[(t + 1) & 1][h0 + ch][b0 + cb * 2] = wv;
        }

        if (t < T_ - 1) {
            // per-group barrier: syncthreads BEFORE arrival (all stores done)
            __syncthreads();
            if (tid == 0) {
                __threadfence();
                unsigned arr = atomicAdd(&g_cnt[bg][0], 1u);
                if (arr == GRP - 1) {
                    g_cnt[bg][0] = 0;
                    asm volatile("st.release.gpu.u32 [%0], %1;"
                                 :: "l"(&g_sns[bg][0]), "r"((unsigned)(t + 1)) : "memory");
                } else {
                    unsigned v;
                    do {
                        asm volatile("ld.acquire.gpu.u32 %0, [%1];"
                                     : "=r"(v) : "l"(&g_sns[bg][0]) : "memory");
                    } while (v < (unsigned)(t + 1));
                }
            }
            __syncthreads();
        } else {
            float* ow = out + (size_t)(b0 + cb * 2) * H_ + h0 + ch;
            ow[0]  = hsum0 * (1.0f / (float)T_);
            ow[H_] = hsum1 * (1.0f / (float)T_);
        }
    }
}

// ---------------------------------------------------------------------------
extern "C" void kernel_launch(void* const* d_in, const int* in_sizes, int n_in,
                              void* d_out, int out_size) {
    const float* x  = (const float*)d_in[0];
    const float* Wz = (const float*)d_in[1];
    const float* Ws = (const float*)d_in[2];
    const float* Wf = (const float*)d_in[3];
    const float* Wo = (const float*)d_in[4];
    const float* Rz = (const float*)d_in[5];
    const float* Rs = (const float*)d_in[6];
    const float* Rf = (const float*)d_in[7];
    const float* Ro = (const float*)d_in[8];
    const float* bz = (const float*)d_in[9];
    const float* bs = (const float*)d_in[10];
    const float* bf = (const float*)d_in[11];
    const float* bo = (const float*)d_in[12];

    const int smem_bytes = (512 * 32 + 2 * 64 * 64 * 2 + 32 * 66) * 4;  // ~139KB
    cudaFuncSetAttribute(lstm_recur,
                         cudaFuncAttributeMaxDynamicSharedMemorySize, smem_bytes);

    lstm_reset<<<1, 32>>>();
    lstm_proj<<<dim3((B_ * T_) / 64, (4 * H_) / 64), 128>>>(
        x, Wz, Ws, Wf, Wo, bz, bs, bf, bo);
    lstm_recur<<<NCTA, 256, smem_bytes>>>(Rz, Rs, Rf, Ro, (float*)d_out);
}

// round 10
// speedup vs baseline: 1.0206x; 1.0206x over previous
#include <cuda_runtime.h>
#include <cstdint>
#include <cmath>

#define B_ 128
#define T_ 512
#define I_ 256
#define H_ 512
#define NCTA 128
#define GRP 64          // CTAs per barrier group (one per b-slice)

// ---- static device scratch ----
__device__ float  g_xproj[(size_t)4 * T_ * B_ * H_];   // [g][t][b][h]
__device__ float2 g_hT[2][H_][B_];                     // h duplicated {v,v}, h-major
__device__ unsigned g_cnt[2][32];                      // per-group barrier counter (padded)
__device__ unsigned g_sns[2][32];                      // per-group barrier sense (persists; self-relative)

// ---- packed fp32x2 FMA ----
__device__ __forceinline__ void fma2(unsigned long long& d,
                                     unsigned long long a,
                                     unsigned long long b) {
    asm("fma.rn.f32x2 %0, %1, %2, %0;" : "+l"(d) : "l"(a), "l"(b));
}
__device__ __forceinline__ float lo32(unsigned long long v) {
    return __uint_as_float((unsigned)(v & 0xffffffffull));
}
__device__ __forceinline__ float hi32(unsigned long long v) {
    return __uint_as_float((unsigned)(v >> 32));
}
__device__ __forceinline__ float rcpa(float x) {
    float r;
    asm("rcp.approx.f32 %0, %1;" : "=f"(r) : "f"(x));
    return r;
}
// rational tanh numerator/denominator (Eigen coefficients, float-accurate)
__device__ __forceinline__ void tanh_pq(float x, float& p, float& q) {
    x = fminf(fmaxf(x, -7.90531110763549805f), 7.90531110763549805f);
    float x2 = x * x;
    float pp = fmaf(x2, -2.76076847742355e-16f, 2.00018790482477e-13f);
    pp = fmaf(pp, x2, -8.60467152213735e-11f);
    pp = fmaf(pp, x2, 5.12229709037114e-08f);
    pp = fmaf(pp, x2, 1.48572235717979e-05f);
    pp = fmaf(pp, x2, 6.37261928875436e-04f);
    pp = fmaf(pp, x2, 4.89352455891786e-03f);
    p = pp * x;
    float qq = fmaf(x2, 1.19825839466702e-06f, 1.18534705686654e-04f);
    qq = fmaf(qq, x2, 2.26843463243900e-03f);
    q = fmaf(qq, x2, 4.89352518554385e-03f);
}
// 4 divisions sharing one rcp.approx
__device__ __forceinline__ void div4(const float* p, const float* q, float* o) {
    float q01 = q[0] * q[1], q23 = q[2] * q[3];
    float r   = rcpa(q01 * q23);
    float r01 = q23 * r, r23 = q01 * r;
    o[0] = p[0] * (q[1] * r01);
    o[1] = p[1] * (q[0] * r01);
    o[2] = p[2] * (q[3] * r23);
    o[3] = p[3] * (q[2] * r23);
}
__device__ __forceinline__ void cpa16(void* sdst, const void* gsrc) {
    unsigned s = (unsigned)__cvta_generic_to_shared(sdst);
    asm volatile("cp.async.cg.shared.global [%0], [%1], 16;" :: "r"(s), "l"(gsrc));
}

// ---------------------------------------------------------------------------
// projection GEMM (proven R6-R8): g_xproj[g][t][b][h] = x.W_g^T + b_g
// ---------------------------------------------------------------------------
__global__ __launch_bounds__(128) void lstm_proj(
    const float* __restrict__ x,
    const float* __restrict__ Wz, const float* __restrict__ Ws,
    const float* __restrict__ Wf, const float* __restrict__ Wo,
    const float* __restrict__ bz, const float* __restrict__ bs,
    const float* __restrict__ bf, const float* __restrict__ bo)
{
    __shared__ __align__(16) float2 As2[32][64];
    __shared__ __align__(16) float  Bs[32][64];

    const int tid = threadIdx.x;
    const int r0  = blockIdx.x * 64;
    const int n0  = blockIdx.y * 64;
    const int g   = n0 >> 9;
    const int h0  = n0 & 511;

    const float* W    = (g == 0) ? Wz : (g == 1) ? Ws : (g == 2) ? Wf : Wo;
    const float* bias = (g == 0) ? bz : (g == 1) ? bs : (g == 2) ? bf : bo;

    const int tn = tid & 7;
    const int tm = tid >> 3;
    const int lm = tid & 63;
    const int qb = (tid >> 6) * 4;
    const float* xr = x + (size_t)(r0 + lm) * I_;
    const float* wr = W + (size_t)(h0 + lm) * I_;

    unsigned long long acc[4][4];
#pragma unroll
    for (int i = 0; i < 4; i++)
#pragma unroll
        for (int j = 0; j < 4; j++) acc[i][j] = 0ull;

    float4 pa[4], pw[4];
#pragma unroll
    for (int i = 0; i < 4; i++) {
        pa[i] = *(const float4*)(xr + (qb + i) * 4);
        pw[i] = *(const float4*)(wr + (qb + i) * 4);
    }

    for (int kt = 0; kt < I_ / 32; kt++) {
#pragma unroll
        for (int i = 0; i < 4; i++) {
            int q = qb + i;
            As2[q * 4 + 0][lm] = make_float2(pa[i].x, pa[i].x);
            As2[q * 4 + 1][lm] = make_float2(pa[i].y, pa[i].y);
            As2[q * 4 + 2][lm] = make_float2(pa[i].z, pa[i].z);
            As2[q * 4 + 3][lm] = make_float2(pa[i].w, pa[i].w);
            Bs[q * 4 + 0][lm] = pw[i].x;
            Bs[q * 4 + 1][lm] = pw[i].y;
            Bs[q * 4 + 2][lm] = pw[i].z;
            Bs[q * 4 + 3][lm] = pw[i].w;
        }
        __syncthreads();
        if (kt + 1 < I_ / 32) {
            int k0 = (kt + 1) * 32;
#pragma unroll
            for (int i = 0; i < 4; i++) {
                pa[i] = *(const float4*)(xr + k0 + (qb + i) * 4);
                pw[i] = *(const float4*)(wr + k0 + (qb + i) * 4);
            }
        }
#pragma unroll
        for (int kk = 0; kk < 32; kk++) {
            ulonglong2 a01 = *(const ulonglong2*)&As2[kk][tm * 4];
            ulonglong2 a23 = *(const ulonglong2*)&As2[kk][tm * 4 + 2];
            ulonglong2 b01 = *(const ulonglong2*)&Bs[kk][tn * 8];
            ulonglong2 b23 = *(const ulonglong2*)&Bs[kk][tn * 8 + 4];
            fma2(acc[0][0], a01.x, b01.x); fma2(acc[0][1], a01.x, b01.y);
            fma2(acc[0][2], a01.x, b23.x); fma2(acc[0][3], a01.x, b23.y);
            fma2(acc[1][0], a01.y, b01.x); fma2(acc[1][1], a01.y, b01.y);
            fma2(acc[1][2], a01.y, b23.x); fma2(acc[1][3], a01.y, b23.y);
            fma2(acc[2][0], a23.x, b01.x); fma2(acc[2][1], a23.x, b01.y);
            fma2(acc[2][2], a23.x, b23.x); fma2(acc[2][3], a23.x, b23.y);
            fma2(acc[3][0], a23.y, b01.x); fma2(acc[3][1], a23.y, b01.y);
            fma2(acc[3][2], a23.y, b23.x); fma2(acc[3][3], a23.y, b23.y);
        }
        __syncthreads();
    }

    float bv[8];
#pragma unroll
    for (int j = 0; j < 8; j++) bv[j] = bias[h0 + tn * 8 + j];
#pragma unroll
    for (int i = 0; i < 4; i++) {
        int r  = r0 + tm * 4 + i;
        int bb = r >> 9;
        int tt = r & 511;
        float* orow = g_xproj + (((size_t)g * T_ + tt) * B_ + bb) * H_ + h0 + tn * 8;
#pragma unroll
        for (int jp = 0; jp < 4; jp++) {
            float2 v = make_float2(lo32(acc[i][jp]) + bv[jp * 2],
                                   hi32(acc[i][jp]) + bv[jp * 2 + 1]);
            *(float2*)(orow + jp * 2) = v;
        }
    }
}

// ---------------------------------------------------------------------------
// persistent recurrence. 128 CTAs x 512 thr (4 warps/SMSP for latency hiding).
// CTA tile: M=32 (4g x 8h), N=64 batch, K=512.
//   Rsm   [512][32] fp32 resident (64KB)
//   Hs2   [2][64][64] float2 dup'd chunks via cp.async (64KB)
//   actsm [32][66] activations (8.4KB)
// Thread micro: 1 m-pair x 2 n -> LDS.64 + LDS.128 + 2 FFMA2 per k.
// ---------------------------------------------------------------------------
__global__ __launch_bounds__(512, 1) void lstm_recur(
    const float* __restrict__ Rz, const float* __restrict__ Rs_,
    const float* __restrict__ Rf, const float* __restrict__ Ro,
    float* __restrict__ out)
{
    extern __shared__ float sm[];
    float*  Rsm   = sm;                               // [512][32]
    float2* Hs2   = (float2*)(sm + 512 * 32);         // [2][64][64]
    float*  actsm = sm + 512 * 32 + 2 * 64 * 64 * 2;  // [32][66]

    const int tid = threadIdx.x;
    const int cta = blockIdx.x;
    const int bg  = cta & 1;
    const int b0  = bg * 64;
    const int h0  = (cta >> 1) * 8;

    const int mg = tid & 15;       // m-pair: rows mg*2, mg*2+1 (M=32)
    const int ng = tid >> 4;       // n-pair: cols ng*2, ng*2+1 (N=64)
    const int gt = mg >> 2;        // gate of this thread's rows
    const int hr = (mg & 3) * 2;   // h-row within tile

    // read barrier sense at entry (self-relative generations; no reset kernel)
    unsigned s0 = 0;
    if (tid == 0) s0 = *(volatile unsigned*)&g_sns[bg][0];

    // ---- load R tile once: Rsm[k][m], m = g*8 + hrow ----
    {
        int m  = tid & 31;
        int kq = (tid >> 5) * 32;
        int rg = m >> 3, hh = m & 7;
        const float* Rp = ((rg == 0) ? Rz : (rg == 1) ? Rs_ : (rg == 2) ? Rf : Ro)
                        + (size_t)(h0 + hh) * H_ + kq;
#pragma unroll
        for (int j = 0; j < 32; j += 4) {
            float4 v = *(const float4*)(Rp + j);
            Rsm[(kq + j + 0) * 32 + m] = v.x;
            Rsm[(kq + j + 1) * 32 + m] = v.y;
            Rsm[(kq + j + 2) * 32 + m] = v.z;
            Rsm[(kq + j + 3) * 32 + m] = v.w;
        }
    }
    __syncthreads();

    // combine identity: this thread owns cell (b0+cn, h0+ch)
    const int ch = tid >> 6;       // 0..7
    const int cn = tid & 63;       // 0..63
    float creg = 0.0f, hsum = 0.0f;

    // cp.async staging: 8 consecutive float2 (4x16B) per thread per chunk
    const int srow = tid >> 3;           // 0..63 (k-row in chunk)
    const int scol = (tid & 7) * 8;      // float2 offset

    for (int t = 0; t < T_; t++) {
        // prefetch xproj for this thread's 4 cells (consumed in epilogue)
        float2 xq0, xq1;
        {
            const float* xb = g_xproj + (((size_t)gt * T_ + t) * B_ + b0 + ng * 2) * H_
                            + h0 + hr;
            xq0 = *(const float2*)xb;
            xq1 = *(const float2*)(xb + H_);
        }

        unsigned long long acc0 = 0, acc1 = 0;

        if (t > 0) {
            const float2* hsrc = &g_hT[t & 1][0][0];
            {   // prologue: chunk 0
                const float2* s = hsrc + (size_t)srow * B_ + b0 + scol;
                float2* d = Hs2 + (size_t)srow * 64 + scol;
#pragma unroll
                for (int i = 0; i < 4; i++) cpa16(d + i * 2, s + i * 2);
                asm volatile("cp.async.commit_group;");
            }
            for (int c = 0; c < 8; c++) {
                asm volatile("cp.async.wait_group 0;");
                __syncthreads();
                if (c < 7) {
                    const float2* s = hsrc + (size_t)((c + 1) * 64 + srow) * B_ + b0 + scol;
                    float2* d = Hs2 + (size_t)(((c + 1) & 1) * 64 + srow) * 64 + scol;
#pragma unroll
                    for (int i = 0; i < 4; i++) cpa16(d + i * 2, s + i * 2);
                    asm volatile("cp.async.commit_group;");
                }
                const float*  Rb = Rsm + (c * 64) * 32 + mg * 2;
                const float2* Hb = Hs2 + (size_t)((c & 1) * 64) * 64 + ng * 2;
#pragma unroll 16
                for (int kk = 0; kk < 64; kk++) {
                    unsigned long long rp = *(const unsigned long long*)(Rb + kk * 32);
                    ulonglong2 hv = *(const ulonglong2*)(Hb + kk * 64);
                    fma2(acc0, rp, hv.x);
                    fma2(acc1, rp, hv.y);
                }
            }
        }

        // ---- epilogue: 4 pre-activations -> rational tanh/sigmoid (branchless) ----
        {
            float pre[4];
            pre[0] = lo32(acc0) + xq0.x;   // row hr,   n0
            pre[1] = hi32(acc0) + xq0.y;   // row hr+1, n0
            pre[2] = lo32(acc1) + xq1.x;   // row hr,   n1
            pre[3] = hi32(acc1) + xq1.y;   // row hr+1, n1

            const bool isz = (gt == 0);
            const float s1  = isz ? 1.0f : 0.5f;   // tanh(x) vs tanh(x/2)
            const float scm = isz ? 1.0f : 0.5f;   // post-scale
            const float sca = isz ? 0.0f : 0.5f;   // post-offset

            float pn[4], qn[4], av[4];
#pragma unroll
            for (int i = 0; i < 4; i++) tanh_pq(pre[i] * s1, pn[i], qn[i]);
            div4(pn, qn, av);
#pragma unroll
            for (int i = 0; i < 4; i++) av[i] = fmaf(av[i], scm, sca);

            actsm[((hr + 0) * 4 + gt) * 66 + ng * 2 + 0] = av[0];
            actsm[((hr + 1) * 4 + gt) * 66 + ng * 2 + 0] = av[1];
            actsm[((hr + 0) * 4 + gt) * 66 + ng * 2 + 1] = av[2];
            actsm[((hr + 1) * 4 + gt) * 66 + ng * 2 + 1] = av[3];
        }
        __syncthreads();

        // ---- combine: 1 cell/thread; c,h update; dup'd h store; h-sum ----
        {
            float z = actsm[(ch * 4 + 0) * 66 + cn];
            float s = actsm[(ch * 4 + 1) * 66 + cn];
            float f = actsm[(ch * 4 + 2) * 66 + cn];
            float o = actsm[(ch * 4 + 3) * 66 + cn];
            float c = fmaf(s, z, f * creg);
            creg = c;
            float p, q;
            tanh_pq(c, p, q);
            float hn = o * (p * rcpa(q));
            hsum += hn;
            g_hT[(t + 1) & 1][h0 + ch][b0 + cn] = make_float2(hn, hn);
        }

        if (t < T_ - 1) {
            __syncthreads();               // all h stores done before arrival
            if (tid == 0) {
                unsigned target = s0 + (unsigned)(t + 1);
                __threadfence();
                unsigned arr = atomicAdd(&g_cnt[bg][0], 1u);
                if (arr == GRP - 1) {
                    g_cnt[bg][0] = 0;
                    asm volatile("st.release.gpu.u32 [%0], %1;"
                                 :: "l"(&g_sns[bg][0]), "r"(target) : "memory");
                } else {
                    unsigned v;
                    do {
                        asm volatile("ld.acquire.gpu.u32 %0, [%1];"
                                     : "=r"(v) : "l"(&g_sns[bg][0]) : "memory");
                    } while ((int)(v - target) < 0);
                }
            }
            __syncthreads();
        } else {
            out[(size_t)(b0 + cn) * H_ + h0 + ch] = hsum * (1.0f / (float)T_);
        }
    }
}

// ---------------------------------------------------------------------------
extern "C" void kernel_launch(void* const* d_in, const int* in_sizes, int n_in,
                              void* d_out, int out_size) {
    const float* x  = (const float*)d_in[0];
    const float* Wz = (const float*)d_in[1];
    const float* Ws = (const float*)d_in[2];
    const float* Wf = (const float*)d_in[3];
    const float* Wo = (const float*)d_in[4];
    const float* Rz = (const float*)d_in[5];
    const float* Rs = (const float*)d_in[6];
    const float* Rf = (const float*)d_in[7];
    const float* Ro = (const float*)d_in[8];
    const float* bz = (const float*)d_in[9];
    const float* bs = (const float*)d_in[10];
    const float* bf = (const float*)d_in[11];
    const float* bo = (const float*)d_in[12];

    const int smem_bytes = (512 * 32 + 2 * 64 * 64 * 2 + 32 * 66) * 4;  // ~139KB
    cudaFuncSetAttribute(lstm_recur,
                         cudaFuncAttributeMaxDynamicSharedMemorySize, smem_bytes);

    lstm_proj<<<dim3((B_ * T_) / 64, (4 * H_) / 64), 128>>>(
        x, Wz, Ws, Wf, Wo, bz, bs, bf, bo);
    lstm_recur<<<NCTA, 512, smem_bytes>>>(Rz, Rs, Rf, Ro, (float*)d_out);
}